// round 16
// baseline (speedup 1.0000x reference)
#include <cuda_runtime.h>
#include <cuda_fp16.h>
#include <math.h>

#define NN 10000
#define EE 256000
#define NBINS 2048
#define RMAXF 3.5f
#define INV_SQRT32 0.17677669529663687f
#define INV_SQRT_NAVG 0.19764235376052372f

struct alignas(8) H4 { __half2 a, b; };

// ---- static device scratch (no allocations allowed) ----
__device__ float   g_featA[NN * 512];
__device__ float   g_featB[NN * 512];
__device__ int     g_deg[NN];
__device__ int     g_degS[NN];
__device__ int     g_rowptr[NN + 1];    // dst CSR
__device__ int     g_rowptrS[NN + 1];   // src CSR
__device__ int     g_cursor[NN];
__device__ int     g_cursorS[NN];
__device__ int     g_pofq[EE];          // q-indexed: dst slot p
__device__ int     g_qofp[EE];          // p-indexed: src slot q
__device__ float   g_eaS[EE * 16];      // q-indexed (edge kernels)
__device__ float   g_eaD[EE * 16];      // p-indexed (agg kernel)
__device__ int2    g_bf[EE];            // q-indexed: {bin, frac-as-int}
__device__ __half2 g_ABh[(long long)EE * 64];   // q-indexed: per lane {A,B1},{B2,B3}
__device__ float   g_msum[EE];          // p-indexed
// packed tables: per (layer,bin,lane) 2 uint4 = {w00,w01,w02,w03},{w11,w12,w13,pad}
__device__ uint4   g_PTv[3 * NBINS * 64];
// final table: per (bin,lane) 1 uint4 = {w0,w1,w2,w3}
__device__ uint4   g_PTFv[NBINS * 32];
__device__ float   g_node[NN];

__device__ __forceinline__ float lerp_h2(unsigned u, float fr) {
    float2 p = __half22float2(*reinterpret_cast<__half2*>(&u));
    return fmaf(fr, p.y, p.x);
}

// ---------------------------------------------------------------------------
__global__ void k_init(const float* __restrict__ x) {
    int idx = blockIdx.x * blockDim.x + threadIdx.x;
    if (idx < NN * 512) {
        int n = idx >> 9;
        int rem = idx & 511;
        int i = rem & 15;
        int c = rem >> 4;
        g_featA[idx] = (i == 0) ? x[n * 32 + c] : 0.f;
    }
    if (idx < NN) { g_deg[idx] = 0; g_degS[idx] = 0; }
}

// ---------------------------------------------------------------------------
__global__ void k_degree(const float* __restrict__ pos,
                         const int* __restrict__ esrc,
                         const int* __restrict__ edst) {
    int e = blockIdx.x * blockDim.x + threadIdx.x;
    if (e >= EE) return;
    int s = esrc[e], d = edst[e];
    float vx = pos[3 * s + 0] - pos[3 * d + 0];
    float vy = pos[3 * s + 1] - pos[3 * d + 1];
    float vz = pos[3 * s + 2] - pos[3 * d + 2];
    float r2 = vx * vx + vy * vy + vz * vz;
    if (r2 < RMAXF * RMAXF) {
        atomicAdd(&g_deg[d], 1);
        atomicAdd(&g_degS[s], 1);
    }
}

// ---------------------------------------------------------------------------
// two single-block exclusive scans (block 0: dst CSR, block 1: src CSR)
// ---------------------------------------------------------------------------
__global__ void k_scan2() {
    __shared__ int part[1024];
    const int PER = 10;  // 1024*10 >= NN
    int* deg = blockIdx.x ? g_degS : g_deg;
    int* rp  = blockIdx.x ? g_rowptrS : g_rowptr;
    int* cur = blockIdx.x ? g_cursorS : g_cursor;
    int t = threadIdx.x;
    int base = t * PER;
    int local[PER];
    int s = 0;
    #pragma unroll
    for (int k = 0; k < PER; k++) {
        int idx = base + k;
        int v = (idx < NN) ? deg[idx] : 0;
        local[k] = s;
        s += v;
    }
    part[t] = s;
    __syncthreads();
    for (int off = 1; off < 1024; off <<= 1) {
        int v = (t >= off) ? part[t - off] : 0;
        __syncthreads();
        part[t] += v;
        __syncthreads();
    }
    int excl = part[t] - s;
    #pragma unroll
    for (int k = 0; k < PER; k++) {
        int idx = base + k;
        if (idx < NN) {
            rp[idx]  = excl + local[k];
            cur[idx] = excl + local[k];
        }
    }
    if (t == 1023) rp[NN] = part[1023];
}

// ---------------------------------------------------------------------------
// scatter: edge record into BOTH orders. ea written twice (src & dst order).
// ---------------------------------------------------------------------------
__global__ void k_scatter(const float* __restrict__ pos,
                          const int* __restrict__ esrc,
                          const int* __restrict__ edst) {
    int e = blockIdx.x * blockDim.x + threadIdx.x;
    if (e >= EE) return;
    int s = esrc[e], d = edst[e];
    float vx = pos[3 * s + 0] - pos[3 * d + 0];
    float vy = pos[3 * s + 1] - pos[3 * d + 1];
    float vz = pos[3 * s + 2] - pos[3 * d + 2];
    float r2 = vx * vx + vy * vy + vz * vz;
    if (r2 >= RMAXF * RMAXF) return;
    float r = sqrtf(r2);
    float inv = 1.f / (r + 1e-9f);
    float X = vx * inv, Y = vy * inv, Z = vz * inv;
    float cut = 0.5f * (cosf(3.14159265358979f * (r / RMAXF)) + 1.f);

    const float S3 = 1.7320508075688772f;
    const float S15 = 3.872983346207417f;
    const float S5 = 2.23606797749979f;
    const float A4 = 2.091650066335189f;   // sqrt(35/8)
    const float B4 = 10.246950765959598f;  // sqrt(105)
    const float C4 = 1.6201851746019651f;  // sqrt(21/8)
    const float D4 = 1.3228756555322954f;  // sqrt(7)/2

    float X2 = X * X, Y2 = Y * Y, Z2 = Z * Z;

    int p = atomicAdd(&g_cursor[d], 1);
    int q = atomicAdd(&g_cursorS[s], 1);
    g_pofq[q] = p;
    g_qofp[p] = q;

    float bf = r * ((float)(NBINS - 1) / RMAXF);
    int bi = (int)bf;
    if (bi > NBINS - 2) bi = NBINS - 2;
    g_bf[q] = make_int2(bi, __float_as_int(bf - (float)bi));

    float4 e0 = make_float4(cut * 1.f, cut * S3 * X, cut * S3 * Y, cut * S3 * Z);
    float4 e1 = make_float4(cut * S15 * X * Y, cut * S15 * Y * Z,
                            cut * 0.5f * S5 * (3.f * Z2 - 1.f), cut * S15 * X * Z);
    float4 e2 = make_float4(cut * 0.5f * S15 * (X2 - Y2),
                            cut * A4 * Y * (3.f * X2 - Y2),
                            cut * B4 * X * Y * Z,
                            cut * C4 * Y * (5.f * Z2 - 1.f));
    float4 e3 = make_float4(cut * D4 * Z * (5.f * Z2 - 3.f),
                            cut * C4 * X * (5.f * Z2 - 1.f),
                            cut * 0.5f * B4 * Z * (X2 - Y2),
                            cut * A4 * X * (X2 - 3.f * Y2));
    float4* es = (float4*)(g_eaS + (long long)q * 16);
    es[0] = e0; es[1] = e1; es[2] = e2; es[3] = e3;
    float4* ed = (float4*)(g_eaD + (long long)p * 16);
    ed[0] = e0; ed[1] = e1; ed[2] = e2; ed[3] = e3;
}

// ---------------------------------------------------------------------------
// radial-MLP lookup tables (fp16 lerp pairs, PACKED layout):
// blockIdx.x = bin, blockIdx.y = layer 0..2 | 3 = final.
// Layer tables: (bin,lane) -> 8 __half2 slots {w00,w01,w02,w03,w11,w12,w13,0}
// Final table:  (bin,lane) -> 4 __half2 slots {w0,w1,w2,w3}
// ---------------------------------------------------------------------------
__global__ void k_table(const float* __restrict__ Wr1, const float* __restrict__ Wr2,
                        const float* __restrict__ Wf1, const float* __restrict__ Wf2) {
    int bin = blockIdx.x, m = blockIdx.y, t = threadIdx.x;
    const float dr = RMAXF / (float)(NBINS - 1);
    float r0 = (float)bin * dr;
    float r1 = (bin + 1 < NBINS) ? (float)(bin + 1) * dr : r0;
    __shared__ float s_h0[64], s_h1[64];
    const float* W1 = (m < 3) ? (Wr1 + m * 640) : Wf1;
    {
        const float step = RMAXF / 9.f;
        const float C = 3.1622776601683795f / 1.12f;  // sqrt(10)/1.12
        float pre0 = 0.f, pre1 = 0.f;
        #pragma unroll
        for (int j = 0; j < 10; j++) {
            float cj = (float)j * step;
            float u0 = (r0 - cj) / step;
            float u1 = (r1 - cj) / step;
            float w = W1[j * 64 + t];
            pre0 += expf(-u0 * u0) * C * w;
            pre1 += expf(-u1 * u1) * C * w;
        }
        pre0 *= 0.31622776601683794f;  // 1/sqrt(10)
        pre1 *= 0.31622776601683794f;
        s_h0[t] = pre0 / (1.f + expf(-pre0));  // silu
        s_h1[t] = pre1 / (1.f + expf(-pre1));
    }
    __syncthreads();
    if (m < 3) {
        const float* W2 = Wr2 + m * 64 * 256;
        __half2* basep = (__half2*)(g_PTv + ((long long)m * NBINS + bin) * 64);
        for (int j = t; j < 256; j += 64) {
            float v0 = 0.f, v1 = 0.f;
            #pragma unroll 8
            for (int k = 0; k < 64; k++) {
                float w = W2[k * 256 + j];
                v0 += s_h0[k] * w;
                v1 += s_h1[k] * w;
            }
            v0 *= 0.125f; v1 *= 0.125f;
            int slot = j >> 5, lane = j & 31;
            if (slot == 4) {
                basep[lane * 8 + 7] = __floats2half2_rn(0.f, 0.f);  // pad (w10 unused)
            } else {
                int s = (slot < 4) ? slot : slot - 1;
                basep[lane * 8 + s] = __floats2half2_rn(v0, v1 - v0);
            }
        }
    } else {
        __half2* basep = (__half2*)(g_PTFv + (long long)bin * 32);
        for (int j = t; j < 128; j += 64) {
            float v0 = 0.f, v1 = 0.f;
            #pragma unroll 8
            for (int k = 0; k < 64; k++) {
                float w = Wf2[k * 128 + j];
                v0 += s_h0[k] * w;
                v1 += s_h1[k] * w;
            }
            v0 *= 0.125f; v1 *= 0.125f;
            int slot = j >> 5, lane = j & 31;
            basep[lane * 4 + slot] = __floats2half2_rn(v0, v1 - v0);
        }
    }
}

// ---------------------------------------------------------------------------
// per-layer edge kernel: ONE WARP PER SOURCE NODE (src-sorted storage).
// Packed table: per edge only 2x LDG.128 (table) + 1x LDG.64 (bin/frac).
// ---------------------------------------------------------------------------
__global__ void __launch_bounds__(256) k_edge(int curBuf, int layer) {
    int gw = (blockIdx.x * blockDim.x + threadIdx.x) >> 5;  // global warp = src node
    int warp = threadIdx.x >> 5;
    int lane = threadIdx.x & 31;
    if (gw >= NN) return;
    int e0 = g_rowptrS[gw], e1 = g_rowptrS[gw + 1];
    if (e0 == e1) return;

    const float* feat = curBuf ? g_featB : g_featA;
    const uint4* tbl = g_PTv + (long long)layer * NBINS * 64 + lane * 2;
    __shared__ float s_ea[8][64];

    const float4* fp = (const float4*)(feat + (long long)gw * 512 + lane * 16);
    float4 f0 = fp[0], f1 = fp[1], f2 = fp[2], f3 = fp[3];
    float xs0 = f0.x;

    for (int base = e0; base < e1; base += 4) {
        int nb = min(4, e1 - base);
        for (int k = lane; k < nb * 16; k += 32)
            s_ea[warp][k] = g_eaS[(long long)base * 16 + k];
        __syncwarp();
        for (int j = 0; j < nb; j++) {
            int q = base + j;
            const float* ea = &s_ea[warp][j * 16];
            float d1 = f0.y * ea[1] + f0.z * ea[2] + f0.w * ea[3];
            float d2 = f1.x * ea[4] + f1.y * ea[5] + f1.z * ea[6] + f1.w * ea[7] + f2.x * ea[8];
            float d3 = f2.y * ea[9] + f2.z * ea[10] + f2.w * ea[11] + f3.x * ea[12] +
                       f3.y * ea[13] + f3.z * ea[14] + f3.w * ea[15];
            int2 bf = g_bf[q];
            float fr = __int_as_float(bf.y);
            const uint4* rowv = tbl + (long long)bf.x * 64;
            uint4 c0 = rowv[0];
            uint4 c1 = rowv[1];
            float w00 = lerp_h2(c0.x, fr);
            float w01 = lerp_h2(c0.y, fr);
            float w02 = lerp_h2(c0.z, fr);
            float w03 = lerp_h2(c0.w, fr);
            float w11 = lerp_h2(c1.x, fr);
            float w12 = lerp_h2(c1.y, fr);
            float w13 = lerp_h2(c1.z, fr);
            float A = w00 * xs0 * ea[0] + w11 * d1 + w12 * d2 + w13 * d3;
            H4 h;
            h.a = __floats2half2_rn(A, w01 * xs0);
            h.b = __floats2half2_rn(w02 * xs0, w03 * xs0);
            *((H4*)(g_ABh + (long long)q * 64 + lane * 2)) = h;
        }
        __syncwarp();
    }
}

// ---------------------------------------------------------------------------
// per-layer node kernel: ONE WARP PER DST NODE, lane = output channel.
// Barrier-free hot loop: AB read contiguous 256B/edge, ea via shfl broadcast,
// 16 register accumulators; self-connection GEMM from smem Wsc (+feat smem).
// ---------------------------------------------------------------------------
#define AGGW 8
__global__ void __launch_bounds__(256) k_agg(int curBuf, const float* __restrict__ Wsc) {
    int t = threadIdx.x, warp = t >> 5, lane = t & 31;
    __shared__ float s_w[4096];
    __shared__ float s_feat[AGGW][512];
    for (int g = t; g < 4096; g += 256) s_w[g] = Wsc[g];
    __syncthreads();

    int n = blockIdx.x * AGGW + warp;
    if (n >= NN) return;
    const float* featC = curBuf ? g_featB : g_featA;
    float* featN = curBuf ? g_featA : g_featB;

    // feat row -> smem (coalesced), read back by broadcast
    {
        float4* sf4 = (float4*)s_feat[warp];
        const float4* gf4 = (const float4*)(featC + (long long)n * 512);
        for (int k = lane; k < 128; k += 32) sf4[k] = gf4[k];
    }
    __syncwarp();

    // self-connection GEMM: sc[i] = sum_cc feat[cc][i] * Wsc[l(i)][cc][lane]
    float sc[16];
    #pragma unroll
    for (int i = 0; i < 16; i++) sc[i] = 0.f;
    #pragma unroll 4
    for (int cc = 0; cc < 32; cc++) {
        const float* f = &s_feat[warp][cc * 16];
        const float* w = &s_w[cc * 32 + lane];
        float w0 = w[0], w1 = w[1024], w2 = w[2048], w3 = w[3072];
        sc[0] += f[0] * w0;
        sc[1] += f[1] * w1;  sc[2] += f[2] * w1;  sc[3] += f[3] * w1;
        #pragma unroll
        for (int i = 4; i < 9; i++)  sc[i] += f[i] * w2;
        #pragma unroll
        for (int i = 9; i < 16; i++) sc[i] += f[i] * w3;
    }

    // edge aggregation (barrier-free)
    float acc[16];
    #pragma unroll
    for (int i = 0; i < 16; i++) acc[i] = 0.f;
    int e0 = g_rowptr[n], e1 = g_rowptr[n + 1];
    for (int p = e0; p < e1; p++) {
        int q = __ldg(&g_qofp[p]);
        H4 h = *((const H4*)(g_ABh + (long long)q * 64 + lane * 2));
        float2 ab  = __half22float2(h.a);   // {A, B1}
        float2 b23 = __half22float2(h.b);   // {B2, B3}
        float myea = (lane < 16) ? g_eaD[(long long)p * 16 + lane] : 0.f;
        acc[0] += ab.x;
        #pragma unroll
        for (int i = 1; i < 4; i++)  acc[i] += ab.y  * __shfl_sync(0xffffffff, myea, i);
        #pragma unroll
        for (int i = 4; i < 9; i++)  acc[i] += b23.x * __shfl_sync(0xffffffff, myea, i);
        #pragma unroll
        for (int i = 9; i < 16; i++) acc[i] += b23.y * __shfl_sync(0xffffffff, myea, i);
    }

    // gate + store (lane writes 16 consecutive floats)
    float y0 = sc[0] * INV_SQRT32 + acc[0] * INV_SQRT_NAVG;
    float sg = 1.f / (1.f + expf(-y0));
    float out[16];
    out[0] = y0 * sg;
    #pragma unroll
    for (int i = 1; i < 16; i++)
        out[i] = (sc[i] * INV_SQRT32 + acc[i] * INV_SQRT_NAVG) * sg;
    float4* dst = (float4*)(featN + (long long)n * 512 + lane * 16);
    dst[0] = make_float4(out[0], out[1], out[2], out[3]);
    dst[1] = make_float4(out[4], out[5], out[6], out[7]);
    dst[2] = make_float4(out[8], out[9], out[10], out[11]);
    dst[3] = make_float4(out[12], out[13], out[14], out[15]);
}

// ---------------------------------------------------------------------------
// final readout, stage 1: ONE WARP PER SOURCE NODE; packed final table.
// ---------------------------------------------------------------------------
__global__ void __launch_bounds__(256) k_fedge(int curBuf) {
    int gw = (blockIdx.x * blockDim.x + threadIdx.x) >> 5;
    int warp = threadIdx.x >> 5;
    int lane = threadIdx.x & 31;
    if (gw >= NN) return;
    int e0 = g_rowptrS[gw], e1 = g_rowptrS[gw + 1];
    if (e0 == e1) return;

    const float* featC = curBuf ? g_featB : g_featA;
    const uint4* tbl = g_PTFv + lane;
    __shared__ float s_ea[8][64];

    const float4* fp = (const float4*)(featC + (long long)gw * 512 + lane * 16);
    float4 f0 = fp[0], f1 = fp[1], f2 = fp[2], f3 = fp[3];

    for (int base = e0; base < e1; base += 4) {
        int nb = min(4, e1 - base);
        for (int k = lane; k < nb * 16; k += 32)
            s_ea[warp][k] = g_eaS[(long long)base * 16 + k];
        __syncwarp();
        for (int j = 0; j < nb; j++) {
            int q = base + j;
            const float* ea = &s_ea[warp][j * 16];
            float d1 = f0.y * ea[1] + f0.z * ea[2] + f0.w * ea[3];
            float d2 = f1.x * ea[4] + f1.y * ea[5] + f1.z * ea[6] + f1.w * ea[7] + f2.x * ea[8];
            float d3 = f2.y * ea[9] + f2.z * ea[10] + f2.w * ea[11] + f3.x * ea[12] +
                       f3.y * ea[13] + f3.z * ea[14] + f3.w * ea[15];
            int2 bf = g_bf[q];
            float fr = __int_as_float(bf.y);
            uint4 c = tbl[(long long)bf.x * 32];
            float w0 = lerp_h2(c.x, fr);
            float w1 = lerp_h2(c.y, fr);
            float w2 = lerp_h2(c.z, fr);
            float w3 = lerp_h2(c.w, fr);
            float v = w0 * f0.x * ea[0] + w1 * d1 + w2 * d2 + w3 * d3;
            #pragma unroll
            for (int off = 16; off; off >>= 1) v += __shfl_down_sync(0xffffffff, v, off);
            if (lane == 0) g_msum[g_pofq[q]] = v;
        }
        __syncwarp();
    }
}

// final readout, stage 2: contiguous per-node sum
__global__ void k_node() {
    int n = blockIdx.x * blockDim.x + threadIdx.x;
    if (n >= NN) return;
    int e0 = g_rowptr[n], e1 = g_rowptr[n + 1];
    float s = 0.f;
    for (int e = e0; e < e1; e++) s += g_msum[e];
    g_node[n] = s * (INV_SQRT32 * INV_SQRT_NAVG);
}

// ---------------------------------------------------------------------------
__global__ void k_out(const int* __restrict__ batch, float* __restrict__ out) {
    __shared__ float s[16];
    int t = threadIdx.x;
    if (t < 16) s[t] = 0.f;
    __syncthreads();
    for (int n = t; n < NN; n += blockDim.x) atomicAdd(&s[batch[n]], g_node[n]);
    __syncthreads();
    if (t < 16) out[t] = s[t] * INV_SQRT_NAVG;
}

// ---------------------------------------------------------------------------
extern "C" void kernel_launch(void* const* d_in, const int* in_sizes, int n_in,
                              void* d_out, int out_size) {
    const float* pos  = (const float*)d_in[0];
    const float* x    = (const float*)d_in[1];
    const int*   batch= (const int*)d_in[2];
    const int*   esrc = (const int*)d_in[3];
    const int*   edst = (const int*)d_in[4];
    const float* Wsc  = (const float*)d_in[5];
    const float* Wr1  = (const float*)d_in[6];
    const float* Wr2  = (const float*)d_in[7];
    const float* Wf1  = (const float*)d_in[8];
    const float* Wf2  = (const float*)d_in[9];
    float* out = (float*)d_out;

    k_init<<<(NN * 512 + 255) / 256, 256>>>(x);
    k_degree<<<(EE + 255) / 256, 256>>>(pos, esrc, edst);
    k_scan2<<<2, 1024>>>();
    k_scatter<<<(EE + 255) / 256, 256>>>(pos, esrc, edst);
    k_table<<<dim3(NBINS, 4), 64>>>(Wr1, Wr2, Wf1, Wf2);

    int egrid = (NN + 7) / 8;   // one warp per src node, 8 warps/block
    // layer 0: A -> B ; layer 1: B -> A ; layer 2: A -> B
    int cur = 0;
    for (int L = 0; L < 3; L++) {
        k_edge<<<egrid, 256>>>(cur, L);
        k_agg<<<(NN + AGGW - 1) / AGGW, 256>>>(cur, Wsc + (long long)L * 4 * 32 * 32);
        cur ^= 1;
    }
    k_fedge<<<egrid, 256>>>(cur);   // cur == 1 -> featB
    k_node<<<(NN + 255) / 256, 256>>>();
    k_out<<<1, 1024>>>(batch, out);
}

// round 17
// speedup vs baseline: 1.0693x; 1.0693x over previous
#include <cuda_runtime.h>
#include <cuda_fp16.h>
#include <math.h>

#define NN 10000
#define EE 256000
#define NBINS 512
#define RMAXF 3.5f
#define INV_SQRT32 0.17677669529663687f
#define INV_SQRT_NAVG 0.19764235376052372f

struct alignas(8) H4 { __half2 a, b; };

// ---- static device scratch (no allocations allowed) ----
__device__ float   g_featA[NN * 512];
__device__ float   g_featB[NN * 512];
__device__ int     g_deg[NN];
__device__ int     g_degS[NN];
__device__ int     g_rowptr[NN + 1];    // dst CSR
__device__ int     g_rowptrS[NN + 1];   // src CSR
__device__ int     g_cursor[NN];
__device__ int     g_cursorS[NN];
__device__ int     g_pofq[EE];          // q-indexed: dst slot p
__device__ int     g_qofp[EE];          // p-indexed: src slot q
__device__ float   g_eaS[EE * 16];      // q-indexed (edge kernels)
__device__ float   g_eaD[EE * 16];      // p-indexed (agg kernel)
__device__ int2    g_bf[EE];            // q-indexed: {bin, frac-as-int}
__device__ __half2 g_ABh[(long long)EE * 64];   // q-indexed: per lane {A,B1},{B2,B3}
__device__ float   g_msum[EE];          // p-indexed
__device__ __half2 g_PTh[3 * NBINS * 256];      // (v, delta) lerp pairs, fp16
__device__ __half2 g_PTFh[NBINS * 128];
__device__ float   g_node[NN];

// ---------------------------------------------------------------------------
__global__ void k_init(const float* __restrict__ x) {
    int idx = blockIdx.x * blockDim.x + threadIdx.x;
    if (idx < NN * 512) {
        int n = idx >> 9;
        int rem = idx & 511;
        int i = rem & 15;
        int c = rem >> 4;
        g_featA[idx] = (i == 0) ? x[n * 32 + c] : 0.f;
    }
    if (idx < NN) { g_deg[idx] = 0; g_degS[idx] = 0; }
}

// ---------------------------------------------------------------------------
__global__ void k_degree(const float* __restrict__ pos,
                         const int* __restrict__ esrc,
                         const int* __restrict__ edst) {
    int e = blockIdx.x * blockDim.x + threadIdx.x;
    if (e >= EE) return;
    int s = esrc[e], d = edst[e];
    float vx = pos[3 * s + 0] - pos[3 * d + 0];
    float vy = pos[3 * s + 1] - pos[3 * d + 1];
    float vz = pos[3 * s + 2] - pos[3 * d + 2];
    float r2 = vx * vx + vy * vy + vz * vz;
    if (r2 < RMAXF * RMAXF) {
        atomicAdd(&g_deg[d], 1);
        atomicAdd(&g_degS[s], 1);
    }
}

// ---------------------------------------------------------------------------
// two single-block exclusive scans (block 0: dst CSR, block 1: src CSR)
// ---------------------------------------------------------------------------
__global__ void k_scan2() {
    __shared__ int part[1024];
    const int PER = 10;  // 1024*10 >= NN
    int* deg = blockIdx.x ? g_degS : g_deg;
    int* rp  = blockIdx.x ? g_rowptrS : g_rowptr;
    int* cur = blockIdx.x ? g_cursorS : g_cursor;
    int t = threadIdx.x;
    int base = t * PER;
    int local[PER];
    int s = 0;
    #pragma unroll
    for (int k = 0; k < PER; k++) {
        int idx = base + k;
        int v = (idx < NN) ? deg[idx] : 0;
        local[k] = s;
        s += v;
    }
    part[t] = s;
    __syncthreads();
    for (int off = 1; off < 1024; off <<= 1) {
        int v = (t >= off) ? part[t - off] : 0;
        __syncthreads();
        part[t] += v;
        __syncthreads();
    }
    int excl = part[t] - s;
    #pragma unroll
    for (int k = 0; k < PER; k++) {
        int idx = base + k;
        if (idx < NN) {
            rp[idx]  = excl + local[k];
            cur[idx] = excl + local[k];
        }
    }
    if (t == 1023) rp[NN] = part[1023];
}

// ---------------------------------------------------------------------------
// scatter: edge record into BOTH orders. ea written twice (src & dst order).
// ---------------------------------------------------------------------------
__global__ void k_scatter(const float* __restrict__ pos,
                          const int* __restrict__ esrc,
                          const int* __restrict__ edst) {
    int e = blockIdx.x * blockDim.x + threadIdx.x;
    if (e >= EE) return;
    int s = esrc[e], d = edst[e];
    float vx = pos[3 * s + 0] - pos[3 * d + 0];
    float vy = pos[3 * s + 1] - pos[3 * d + 1];
    float vz = pos[3 * s + 2] - pos[3 * d + 2];
    float r2 = vx * vx + vy * vy + vz * vz;
    if (r2 >= RMAXF * RMAXF) return;
    float r = sqrtf(r2);
    float inv = 1.f / (r + 1e-9f);
    float X = vx * inv, Y = vy * inv, Z = vz * inv;
    float cut = 0.5f * (cosf(3.14159265358979f * (r / RMAXF)) + 1.f);

    const float S3 = 1.7320508075688772f;
    const float S15 = 3.872983346207417f;
    const float S5 = 2.23606797749979f;
    const float A4 = 2.091650066335189f;   // sqrt(35/8)
    const float B4 = 10.246950765959598f;  // sqrt(105)
    const float C4 = 1.6201851746019651f;  // sqrt(21/8)
    const float D4 = 1.3228756555322954f;  // sqrt(7)/2

    float X2 = X * X, Y2 = Y * Y, Z2 = Z * Z;

    int p = atomicAdd(&g_cursor[d], 1);
    int q = atomicAdd(&g_cursorS[s], 1);
    g_pofq[q] = p;
    g_qofp[p] = q;

    float bf = r * ((float)(NBINS - 1) / RMAXF);
    int bi = (int)bf;
    if (bi > NBINS - 2) bi = NBINS - 2;
    g_bf[q] = make_int2(bi, __float_as_int(bf - (float)bi));

    float4 e0 = make_float4(cut * 1.f, cut * S3 * X, cut * S3 * Y, cut * S3 * Z);
    float4 e1 = make_float4(cut * S15 * X * Y, cut * S15 * Y * Z,
                            cut * 0.5f * S5 * (3.f * Z2 - 1.f), cut * S15 * X * Z);
    float4 e2 = make_float4(cut * 0.5f * S15 * (X2 - Y2),
                            cut * A4 * Y * (3.f * X2 - Y2),
                            cut * B4 * X * Y * Z,
                            cut * C4 * Y * (5.f * Z2 - 1.f));
    float4 e3 = make_float4(cut * D4 * Z * (5.f * Z2 - 3.f),
                            cut * C4 * X * (5.f * Z2 - 1.f),
                            cut * 0.5f * B4 * Z * (X2 - Y2),
                            cut * A4 * X * (X2 - 3.f * Y2));
    float4* es = (float4*)(g_eaS + (long long)q * 16);
    es[0] = e0; es[1] = e1; es[2] = e2; es[3] = e3;
    float4* ed = (float4*)(g_eaD + (long long)p * 16);
    ed[0] = e0; ed[1] = e1; ed[2] = e2; ed[3] = e3;
}

// ---------------------------------------------------------------------------
// radial-MLP lookup tables (fp16 lerp pairs, pack fused):
// blockIdx.x = bin, blockIdx.y = layer 0..2 | 3 = final.
// ---------------------------------------------------------------------------
__global__ void k_table(const float* __restrict__ Wr1, const float* __restrict__ Wr2,
                        const float* __restrict__ Wf1, const float* __restrict__ Wf2) {
    int bin = blockIdx.x, m = blockIdx.y, t = threadIdx.x;
    const float dr = RMAXF / (float)(NBINS - 1);
    float r0 = (float)bin * dr;
    float r1 = (bin + 1 < NBINS) ? (float)(bin + 1) * dr : r0;
    __shared__ float s_h0[64], s_h1[64];
    const float* W1 = (m < 3) ? (Wr1 + m * 640) : Wf1;
    {
        const float step = RMAXF / 9.f;
        const float C = 3.1622776601683795f / 1.12f;  // sqrt(10)/1.12
        float pre0 = 0.f, pre1 = 0.f;
        #pragma unroll
        for (int j = 0; j < 10; j++) {
            float cj = (float)j * step;
            float u0 = (r0 - cj) / step;
            float u1 = (r1 - cj) / step;
            float w = W1[j * 64 + t];
            pre0 += expf(-u0 * u0) * C * w;
            pre1 += expf(-u1 * u1) * C * w;
        }
        pre0 *= 0.31622776601683794f;  // 1/sqrt(10)
        pre1 *= 0.31622776601683794f;
        s_h0[t] = pre0 / (1.f + expf(-pre0));  // silu
        s_h1[t] = pre1 / (1.f + expf(-pre1));
    }
    __syncthreads();
    if (m < 3) {
        const float* W2 = Wr2 + m * 64 * 256;
        for (int j = t; j < 256; j += 64) {
            float v0 = 0.f, v1 = 0.f;
            #pragma unroll 8
            for (int k = 0; k < 64; k++) {
                float w = W2[k * 256 + j];
                v0 += s_h0[k] * w;
                v1 += s_h1[k] * w;
            }
            v0 *= 0.125f; v1 *= 0.125f;
            g_PTh[((long long)m * NBINS + bin) * 256 + j] = __floats2half2_rn(v0, v1 - v0);
        }
    } else {
        for (int j = t; j < 128; j += 64) {
            float v0 = 0.f, v1 = 0.f;
            #pragma unroll 8
            for (int k = 0; k < 64; k++) {
                float w = Wf2[k * 128 + j];
                v0 += s_h0[k] * w;
                v1 += s_h1[k] * w;
            }
            v0 *= 0.125f; v1 *= 0.125f;
            g_PTFh[bin * 128 + j] = __floats2half2_rn(v0, v1 - v0);
        }
    }
}

// ---------------------------------------------------------------------------
// per-layer edge kernel: ONE WARP PER SOURCE NODE (src-sorted storage).
// ---------------------------------------------------------------------------
__global__ void __launch_bounds__(256) k_edge(int curBuf, int layer) {
    int gw = (blockIdx.x * blockDim.x + threadIdx.x) >> 5;  // global warp = src node
    int warp = threadIdx.x >> 5;
    int lane = threadIdx.x & 31;
    if (gw >= NN) return;
    int e0 = g_rowptrS[gw], e1 = g_rowptrS[gw + 1];
    if (e0 == e1) return;

    const float* feat = curBuf ? g_featB : g_featA;
    const __half2* tbl = g_PTh + (long long)layer * NBINS * 256;
    __shared__ float s_ea[8][64];

    const float4* fp = (const float4*)(feat + (long long)gw * 512 + lane * 16);
    float4 f0 = fp[0], f1 = fp[1], f2 = fp[2], f3 = fp[3];
    float xs0 = f0.x;

    for (int base = e0; base < e1; base += 4) {
        int nb = min(4, e1 - base);
        for (int k = lane; k < nb * 16; k += 32)
            s_ea[warp][k] = g_eaS[(long long)base * 16 + k];
        __syncwarp();
        for (int j = 0; j < nb; j++) {
            int q = base + j;
            const float* ea = &s_ea[warp][j * 16];
            float d1 = f0.y * ea[1] + f0.z * ea[2] + f0.w * ea[3];
            float d2 = f1.x * ea[4] + f1.y * ea[5] + f1.z * ea[6] + f1.w * ea[7] + f2.x * ea[8];
            float d3 = f2.y * ea[9] + f2.z * ea[10] + f2.w * ea[11] + f3.x * ea[12] +
                       f3.y * ea[13] + f3.z * ea[14] + f3.w * ea[15];
            int2 bf = g_bf[q];
            float fr = __int_as_float(bf.y);
            const __half2* row = tbl + (long long)bf.x * 256;
            float2 pw;
            pw = __half22float2(row[lane]);        float w00 = pw.x + fr * pw.y;
            pw = __half22float2(row[32 + lane]);   float w01 = pw.x + fr * pw.y;
            pw = __half22float2(row[64 + lane]);   float w02 = pw.x + fr * pw.y;
            pw = __half22float2(row[96 + lane]);   float w03 = pw.x + fr * pw.y;
            pw = __half22float2(row[160 + lane]);  float w11 = pw.x + fr * pw.y;
            pw = __half22float2(row[192 + lane]);  float w12 = pw.x + fr * pw.y;
            pw = __half22float2(row[224 + lane]);  float w13 = pw.x + fr * pw.y;
            float A = w00 * xs0 * ea[0] + w11 * d1 + w12 * d2 + w13 * d3;
            H4 h;
            h.a = __floats2half2_rn(A, w01 * xs0);
            h.b = __floats2half2_rn(w02 * xs0, w03 * xs0);
            *((H4*)(g_ABh + (long long)q * 64 + lane * 2)) = h;
        }
        __syncwarp();
    }
}

// ---------------------------------------------------------------------------
// per-layer node kernel: ONE WARP PER DST NODE, lane = output channel.
// Barrier-free hot loop: AB read contiguous 256B/edge, ea via shfl broadcast,
// 16 register accumulators; self-connection GEMM from smem Wsc (+feat smem).
// ---------------------------------------------------------------------------
#define AGGW 8
__global__ void __launch_bounds__(256) k_agg(int curBuf, const float* __restrict__ Wsc) {
    int t = threadIdx.x, warp = t >> 5, lane = t & 31;
    __shared__ float s_w[4096];
    __shared__ float s_feat[AGGW][512];
    for (int g = t; g < 4096; g += 256) s_w[g] = Wsc[g];
    __syncthreads();

    int n = blockIdx.x * AGGW + warp;
    if (n >= NN) return;
    const float* featC = curBuf ? g_featB : g_featA;
    float* featN = curBuf ? g_featA : g_featB;

    // feat row -> smem (coalesced), read back by broadcast
    {
        float4* sf4 = (float4*)s_feat[warp];
        const float4* gf4 = (const float4*)(featC + (long long)n * 512);
        for (int k = lane; k < 128; k += 32) sf4[k] = gf4[k];
    }
    __syncwarp();

    // self-connection GEMM: sc[i] = sum_cc feat[cc][i] * Wsc[l(i)][cc][lane]
    float sc[16];
    #pragma unroll
    for (int i = 0; i < 16; i++) sc[i] = 0.f;
    #pragma unroll 4
    for (int cc = 0; cc < 32; cc++) {
        const float* f = &s_feat[warp][cc * 16];
        const float* w = &s_w[cc * 32 + lane];
        float w0 = w[0], w1 = w[1024], w2 = w[2048], w3 = w[3072];
        sc[0] += f[0] * w0;
        sc[1] += f[1] * w1;  sc[2] += f[2] * w1;  sc[3] += f[3] * w1;
        #pragma unroll
        for (int i = 4; i < 9; i++)  sc[i] += f[i] * w2;
        #pragma unroll
        for (int i = 9; i < 16; i++) sc[i] += f[i] * w3;
    }

    // edge aggregation (barrier-free)
    float acc[16];
    #pragma unroll
    for (int i = 0; i < 16; i++) acc[i] = 0.f;
    int e0 = g_rowptr[n], e1 = g_rowptr[n + 1];
    for (int p = e0; p < e1; p++) {
        int q = __ldg(&g_qofp[p]);
        H4 h = *((const H4*)(g_ABh + (long long)q * 64 + lane * 2));
        float2 ab  = __half22float2(h.a);   // {A, B1}
        float2 b23 = __half22float2(h.b);   // {B2, B3}
        float myea = (lane < 16) ? g_eaD[(long long)p * 16 + lane] : 0.f;
        acc[0] += ab.x;
        #pragma unroll
        for (int i = 1; i < 4; i++)  acc[i] += ab.y  * __shfl_sync(0xffffffff, myea, i);
        #pragma unroll
        for (int i = 4; i < 9; i++)  acc[i] += b23.x * __shfl_sync(0xffffffff, myea, i);
        #pragma unroll
        for (int i = 9; i < 16; i++) acc[i] += b23.y * __shfl_sync(0xffffffff, myea, i);
    }

    // gate + store (lane writes 16 consecutive floats)
    float y0 = sc[0] * INV_SQRT32 + acc[0] * INV_SQRT_NAVG;
    float sg = 1.f / (1.f + expf(-y0));
    float out[16];
    out[0] = y0 * sg;
    #pragma unroll
    for (int i = 1; i < 16; i++)
        out[i] = (sc[i] * INV_SQRT32 + acc[i] * INV_SQRT_NAVG) * sg;
    float4* dst = (float4*)(featN + (long long)n * 512 + lane * 16);
    dst[0] = make_float4(out[0], out[1], out[2], out[3]);
    dst[1] = make_float4(out[4], out[5], out[6], out[7]);
    dst[2] = make_float4(out[8], out[9], out[10], out[11]);
    dst[3] = make_float4(out[12], out[13], out[14], out[15]);
}

// ---------------------------------------------------------------------------
// final readout, stage 1: ONE WARP PER SOURCE NODE (same structure as k_edge)
// ---------------------------------------------------------------------------
__global__ void __launch_bounds__(256) k_fedge(int curBuf) {
    int gw = (blockIdx.x * blockDim.x + threadIdx.x) >> 5;
    int warp = threadIdx.x >> 5;
    int lane = threadIdx.x & 31;
    if (gw >= NN) return;
    int e0 = g_rowptrS[gw], e1 = g_rowptrS[gw + 1];
    if (e0 == e1) return;

    const float* featC = curBuf ? g_featB : g_featA;
    __shared__ float s_ea[8][64];

    const float4* fp = (const float4*)(featC + (long long)gw * 512 + lane * 16);
    float4 f0 = fp[0], f1 = fp[1], f2 = fp[2], f3 = fp[3];

    for (int base = e0; base < e1; base += 4) {
        int nb = min(4, e1 - base);
        for (int k = lane; k < nb * 16; k += 32)
            s_ea[warp][k] = g_eaS[(long long)base * 16 + k];
        __syncwarp();
        for (int j = 0; j < nb; j++) {
            int q = base + j;
            const float* ea = &s_ea[warp][j * 16];
            float d1 = f0.y * ea[1] + f0.z * ea[2] + f0.w * ea[3];
            float d2 = f1.x * ea[4] + f1.y * ea[5] + f1.z * ea[6] + f1.w * ea[7] + f2.x * ea[8];
            float d3 = f2.y * ea[9] + f2.z * ea[10] + f2.w * ea[11] + f3.x * ea[12] +
                       f3.y * ea[13] + f3.z * ea[14] + f3.w * ea[15];
            int2 bf = g_bf[q];
            float fr = __int_as_float(bf.y);
            const __half2* row = g_PTFh + (long long)bf.x * 128;
            float2 pw;
            pw = __half22float2(row[lane]);       float w0 = pw.x + fr * pw.y;
            pw = __half22float2(row[32 + lane]);  float w1 = pw.x + fr * pw.y;
            pw = __half22float2(row[64 + lane]);  float w2 = pw.x + fr * pw.y;
            pw = __half22float2(row[96 + lane]);  float w3 = pw.x + fr * pw.y;
            float v = w0 * f0.x * ea[0] + w1 * d1 + w2 * d2 + w3 * d3;
            #pragma unroll
            for (int off = 16; off; off >>= 1) v += __shfl_down_sync(0xffffffff, v, off);
            if (lane == 0) g_msum[g_pofq[q]] = v;
        }
        __syncwarp();
    }
}

// final readout, stage 2: contiguous per-node sum
__global__ void k_node() {
    int n = blockIdx.x * blockDim.x + threadIdx.x;
    if (n >= NN) return;
    int e0 = g_rowptr[n], e1 = g_rowptr[n + 1];
    float s = 0.f;
    for (int e = e0; e < e1; e++) s += g_msum[e];
    g_node[n] = s * (INV_SQRT32 * INV_SQRT_NAVG);
}

// ---------------------------------------------------------------------------
__global__ void k_out(const int* __restrict__ batch, float* __restrict__ out) {
    __shared__ float s[16];
    int t = threadIdx.x;
    if (t < 16) s[t] = 0.f;
    __syncthreads();
    for (int n = t; n < NN; n += blockDim.x) atomicAdd(&s[batch[n]], g_node[n]);
    __syncthreads();
    if (t < 16) out[t] = s[t] * INV_SQRT_NAVG;
}

// ---------------------------------------------------------------------------
extern "C" void kernel_launch(void* const* d_in, const int* in_sizes, int n_in,
                              void* d_out, int out_size) {
    const float* pos  = (const float*)d_in[0];
    const float* x    = (const float*)d_in[1];
    const int*   batch= (const int*)d_in[2];
    const int*   esrc = (const int*)d_in[3];
    const int*   edst = (const int*)d_in[4];
    const float* Wsc  = (const float*)d_in[5];
    const float* Wr1  = (const float*)d_in[6];
    const float* Wr2  = (const float*)d_in[7];
    const float* Wf1  = (const float*)d_in[8];
    const float* Wf2  = (const float*)d_in[9];
    float* out = (float*)d_out;

    k_init<<<(NN * 512 + 255) / 256, 256>>>(x);
    k_degree<<<(EE + 255) / 256, 256>>>(pos, esrc, edst);
    k_scan2<<<2, 1024>>>();
    k_scatter<<<(EE + 255) / 256, 256>>>(pos, esrc, edst);
    k_table<<<dim3(NBINS, 4), 64>>>(Wr1, Wr2, Wf1, Wf2);

    int egrid = (NN + 7) / 8;   // one warp per src node, 8 warps/block
    // layer 0: A -> B ; layer 1: B -> A ; layer 2: A -> B
    int cur = 0;
    for (int L = 0; L < 3; L++) {
        k_edge<<<egrid, 256>>>(cur, L);
        k_agg<<<(NN + AGGW - 1) / AGGW, 256>>>(cur, Wsc + (long long)L * 4 * 32 * 32);
        cur ^= 1;
    }
    k_fedge<<<egrid, 256>>>(cur);   // cur == 1 -> featB
    k_node<<<(NN + 255) / 256, 256>>>();
    k_out<<<1, 1024>>>(batch, out);
}